// round 1
// baseline (speedup 1.0000x reference)
#include <cuda_runtime.h>

#define B_ 64
#define A_ 512
#define D_ 256
#define H_ 8
#define DH_ 32
#define F_ 512
#define ROWS_ (B_*A_)            // 32768
#define SZ_ ((size_t)ROWS_*D_)   // 8388608 floats per tensor buffer

// Scratch: q,k,v,o,proj,h,h2 (7 x [B,A,D]) + pooled + fc1 + fc2
__device__ float g_scratch[7*8388608 + B_*D_ + 2*B_*F_];

// ---------------------------------------------------------------------------
// SGEMM: C[M,N] = A[M,K] @ W[K,N] + bias[N]  (optional relu)
// 128x128 block tile, 16 k-tile, 256 threads, 8x8 per-thread microtile.
// ---------------------------------------------------------------------------
__global__ __launch_bounds__(256) void sgemm_bias_kernel(
    const float* __restrict__ A, const float* __restrict__ W,
    const float* __restrict__ bias, float* __restrict__ C,
    int M, int N, int K, int relu)
{
  __shared__ float As[16][128];   // As[k][m]
  __shared__ float Bs[16][128];   // Bs[k][n]
  const int tid = threadIdx.x;
  const int bm = blockIdx.y * 128;
  const int bn = blockIdx.x * 128;
  const int tx = tid & 15;        // n-dir
  const int ty = tid >> 4;        // m-dir

  float acc[8][8];
  #pragma unroll
  for (int i = 0; i < 8; i++)
    #pragma unroll
    for (int j = 0; j < 8; j++) acc[i][j] = 0.f;

  for (int k0 = 0; k0 < K; k0 += 16) {
    #pragma unroll
    for (int l = 0; l < 2; l++) {
      int idx = tid + l * 256;                 // 0..511
      // A tile: 128 rows x 16 k, float4 along k, stored transposed
      int r  = idx >> 2;
      int c4 = (idx & 3) << 2;
      int grow = bm + r;
      float4 av = make_float4(0.f, 0.f, 0.f, 0.f);
      if (grow < M) av = *(const float4*)(A + (size_t)grow * K + k0 + c4);
      As[c4 + 0][r] = av.x; As[c4 + 1][r] = av.y;
      As[c4 + 2][r] = av.z; As[c4 + 3][r] = av.w;
      // B tile: 16 k-rows x 128 n
      int r2  = idx >> 5;
      int c42 = (idx & 31) << 2;
      float4 bv = *(const float4*)(W + (size_t)(k0 + r2) * N + bn + c42);
      *(float4*)&Bs[r2][c42] = bv;
    }
    __syncthreads();
    #pragma unroll
    for (int kk = 0; kk < 16; kk++) {
      float a[8], b[8];
      *(float4*)&a[0] = *(const float4*)&As[kk][ty * 8];
      *(float4*)&a[4] = *(const float4*)&As[kk][ty * 8 + 4];
      *(float4*)&b[0] = *(const float4*)&Bs[kk][tx * 8];
      *(float4*)&b[4] = *(const float4*)&Bs[kk][tx * 8 + 4];
      #pragma unroll
      for (int i = 0; i < 8; i++)
        #pragma unroll
        for (int j = 0; j < 8; j++) acc[i][j] += a[i] * b[j];
    }
    __syncthreads();
  }

  #pragma unroll
  for (int i = 0; i < 8; i++) {
    int grow = bm + ty * 8 + i;
    if (grow < M) {
      #pragma unroll
      for (int j4 = 0; j4 < 8; j4 += 4) {
        int gcol = bn + tx * 8 + j4;
        float4 o;
        o.x = acc[i][j4 + 0] + bias[gcol + 0];
        o.y = acc[i][j4 + 1] + bias[gcol + 1];
        o.z = acc[i][j4 + 2] + bias[gcol + 2];
        o.w = acc[i][j4 + 3] + bias[gcol + 3];
        if (relu) {
          o.x = fmaxf(o.x, 0.f); o.y = fmaxf(o.y, 0.f);
          o.z = fmaxf(o.z, 0.f); o.w = fmaxf(o.w, 0.f);
        }
        *(float4*)(C + (size_t)grow * N + gcol) = o;
      }
    }
  }
}

// ---------------------------------------------------------------------------
// Attention: one CTA per (b,h). K^T, V^T in smem (stride 513, conflict-free).
// 8 warps x 64 queries each, 4-query register blocking.
// Score phase: lane owns keys (lane + 32*i). Output phase: lane owns dim d=lane.
// ---------------------------------------------------------------------------
#define KT_STRIDE 513
__global__ __launch_bounds__(256) void attn_kernel(
    const float* __restrict__ Q, const float* __restrict__ K,
    const float* __restrict__ V, float* __restrict__ O)
{
  extern __shared__ float sm[];
  float* Kt = sm;                    // [32][513]
  float* Vt = sm + 32 * KT_STRIDE;   // [32][513]
  const int b = blockIdx.x >> 3;
  const int h = blockIdx.x & 7;
  const int tid = threadIdx.x;
  const int lane = tid & 31;
  const int w = tid >> 5;

  const float* Kb = K + ((size_t)b * A_) * D_ + h * DH_;
  const float* Vb = V + ((size_t)b * A_) * D_ + h * DH_;
  for (int idx = tid; idx < A_ * 8; idx += 256) {
    int kk = idx >> 3;
    int d4 = (idx & 7) << 2;
    float4 kv = *(const float4*)(Kb + (size_t)kk * D_ + d4);
    float4 vv = *(const float4*)(Vb + (size_t)kk * D_ + d4);
    Kt[(d4 + 0) * KT_STRIDE + kk] = kv.x;
    Kt[(d4 + 1) * KT_STRIDE + kk] = kv.y;
    Kt[(d4 + 2) * KT_STRIDE + kk] = kv.z;
    Kt[(d4 + 3) * KT_STRIDE + kk] = kv.w;
    Vt[(d4 + 0) * KT_STRIDE + kk] = vv.x;
    Vt[(d4 + 1) * KT_STRIDE + kk] = vv.y;
    Vt[(d4 + 2) * KT_STRIDE + kk] = vv.z;
    Vt[(d4 + 3) * KT_STRIDE + kk] = vv.w;
  }
  __syncthreads();

  const float scale = 0.17677669529663687f;  // 1/sqrt(32)
  const float* Qb = Q + ((size_t)b * A_) * D_ + h * DH_ + lane;
  float* Ob = O + ((size_t)b * A_) * D_ + h * DH_ + lane;

  for (int g = 0; g < 16; g++) {
    const int q0 = w * 64 + g * 4;
    float qreg[4];
    float sc[4][16];
    #pragma unroll
    for (int m = 0; m < 4; m++) {
      qreg[m] = Qb[(size_t)(q0 + m) * D_] * scale;
      #pragma unroll
      for (int i = 0; i < 16; i++) sc[m][i] = 0.f;
    }

    // scores: sc[m][i] = q_m . K[lane + 32 i]
    for (int d = 0; d < 32; d++) {
      float qv0 = __shfl_sync(0xffffffffu, qreg[0], d);
      float qv1 = __shfl_sync(0xffffffffu, qreg[1], d);
      float qv2 = __shfl_sync(0xffffffffu, qreg[2], d);
      float qv3 = __shfl_sync(0xffffffffu, qreg[3], d);
      const float* kr = &Kt[d * KT_STRIDE + lane];
      #pragma unroll
      for (int i = 0; i < 16; i++) {
        float kv = kr[i * 32];
        sc[0][i] += qv0 * kv;
        sc[1][i] += qv1 * kv;
        sc[2][i] += qv2 * kv;
        sc[3][i] += qv3 * kv;
      }
    }

    // softmax per query (warp-wide over 512 keys)
    float acc[4];
    #pragma unroll
    for (int m = 0; m < 4; m++) {
      float mx = sc[m][0];
      #pragma unroll
      for (int i = 1; i < 16; i++) mx = fmaxf(mx, sc[m][i]);
      #pragma unroll
      for (int o = 16; o; o >>= 1) mx = fmaxf(mx, __shfl_xor_sync(0xffffffffu, mx, o));
      float s = 0.f;
      #pragma unroll
      for (int i = 0; i < 16; i++) {
        float e = __expf(sc[m][i] - mx);
        sc[m][i] = e;
        s += e;
      }
      #pragma unroll
      for (int o = 16; o; o >>= 1) s += __shfl_xor_sync(0xffffffffu, s, o);
      float inv = 1.f / s;
      #pragma unroll
      for (int i = 0; i < 16; i++) sc[m][i] *= inv;
      acc[m] = 0.f;
    }

    // output: lane owns dim d=lane; p broadcast via shfl from key owner
    const float* vr = &Vt[lane * KT_STRIDE];
    #pragma unroll
    for (int i = 0; i < 16; i++) {
      for (int j = 0; j < 32; j++) {
        float vv = vr[i * 32 + j];
        acc[0] += __shfl_sync(0xffffffffu, sc[0][i], j) * vv;
        acc[1] += __shfl_sync(0xffffffffu, sc[1][i], j) * vv;
        acc[2] += __shfl_sync(0xffffffffu, sc[2][i], j) * vv;
        acc[3] += __shfl_sync(0xffffffffu, sc[3][i], j) * vv;
      }
    }
    #pragma unroll
    for (int m = 0; m < 4; m++) Ob[(size_t)(q0 + m) * D_] = acc[m];
  }
}

// ---------------------------------------------------------------------------
// LayerNorm(res + x) * g + b, warp per row of 256.
// ---------------------------------------------------------------------------
__global__ __launch_bounds__(256) void ln_residual_kernel(
    const float* __restrict__ res, const float* __restrict__ x,
    const float* __restrict__ g, const float* __restrict__ bta,
    float* __restrict__ out)
{
  const int gw = (blockIdx.x * 256 + threadIdx.x) >> 5;
  const int lane = threadIdx.x & 31;
  const float* r = res + (size_t)gw * D_;
  const float* xx = x + (size_t)gw * D_;
  float v[8];
  float s = 0.f;
  #pragma unroll
  for (int i = 0; i < 8; i++) {
    v[i] = r[lane + i * 32] + xx[lane + i * 32];
    s += v[i];
  }
  #pragma unroll
  for (int o = 16; o; o >>= 1) s += __shfl_xor_sync(0xffffffffu, s, o);
  float mu = s * (1.f / 256.f);
  float vs = 0.f;
  #pragma unroll
  for (int i = 0; i < 8; i++) { float d = v[i] - mu; vs += d * d; }
  #pragma unroll
  for (int o = 16; o; o >>= 1) vs += __shfl_xor_sync(0xffffffffu, vs, o);
  float inv = rsqrtf(vs * (1.f / 256.f) + 1e-5f);
  float* op = out + (size_t)gw * D_;
  #pragma unroll
  for (int i = 0; i < 8; i++)
    op[lane + i * 32] = (v[i] - mu) * inv * g[lane + i * 32] + bta[lane + i * 32];
}

// ---------------------------------------------------------------------------
// Pooling: w = softmax_a(||h[b,a,:]||); pooled[b,d] = sum_a w_a h[b,a,d]
// one block (256 thr) per batch.
// ---------------------------------------------------------------------------
__global__ __launch_bounds__(256) void pool_kernel(
    const float* __restrict__ h, float* __restrict__ pooled)
{
  __shared__ float wsm[A_];
  __shared__ float rbuf[8];
  const int b = blockIdx.x;
  const int tid = threadIdx.x;
  const int lane = tid & 31;
  const int w = tid >> 5;
  const float* hb = h + (size_t)b * A_ * D_;

  for (int a = w; a < A_; a += 8) {
    float s = 0.f;
    #pragma unroll
    for (int i = 0; i < 8; i++) {
      float v = hb[(size_t)a * D_ + lane + i * 32];
      s += v * v;
    }
    #pragma unroll
    for (int o = 16; o; o >>= 1) s += __shfl_xor_sync(0xffffffffu, s, o);
    if (lane == 0) wsm[a] = sqrtf(s);
  }
  __syncthreads();

  float lm = -1e30f;
  for (int a = tid; a < A_; a += 256) lm = fmaxf(lm, wsm[a]);
  #pragma unroll
  for (int o = 16; o; o >>= 1) lm = fmaxf(lm, __shfl_xor_sync(0xffffffffu, lm, o));
  if (lane == 0) rbuf[w] = lm;
  __syncthreads();
  float mx = rbuf[0];
  #pragma unroll
  for (int i = 1; i < 8; i++) mx = fmaxf(mx, rbuf[i]);
  __syncthreads();  // everyone has mx before rbuf is overwritten

  float ls = 0.f;
  for (int a = tid; a < A_; a += 256) {
    float e = __expf(wsm[a] - mx);
    wsm[a] = e;
    ls += e;
  }
  #pragma unroll
  for (int o = 16; o; o >>= 1) ls += __shfl_xor_sync(0xffffffffu, ls, o);
  if (lane == 0) rbuf[w] = ls;
  __syncthreads();
  float tot = 0.f;
  #pragma unroll
  for (int i = 0; i < 8; i++) tot += rbuf[i];
  float inv = 1.f / tot;

  const int d = tid;  // 256 threads, D_=256
  float accd = 0.f;
  for (int a = 0; a < A_; a++) accd += wsm[a] * hb[(size_t)a * D_ + d];
  pooled[(size_t)b * D_ + d] = accd * inv;
}

// ---------------------------------------------------------------------------
// Final head: out[64,2] = h2 @ W_out + b_out
// ---------------------------------------------------------------------------
__global__ void fcout_kernel(const float* __restrict__ h2,
                             const float* __restrict__ Wo,
                             const float* __restrict__ bo,
                             float* __restrict__ out)
{
  int idx = threadIdx.x;
  if (idx >= B_ * 2) return;
  int m = idx >> 1, n = idx & 1;
  float acc = bo[n];
  for (int k = 0; k < F_; k++) acc += h2[(size_t)m * F_ + k] * Wo[k * 2 + n];
  out[idx] = acc;
}

// ---------------------------------------------------------------------------
extern "C" void kernel_launch(void* const* d_in, const int* in_sizes, int n_in,
                              void* d_out, int out_size)
{
  const float* trg   = (const float*)d_in[0];
  const float* src   = (const float*)d_in[1];
  const float* W_sa  = (const float*)d_in[2];
  const float* b_sa  = (const float*)d_in[3];
  const float* W_ea  = (const float*)d_in[4];
  const float* b_ea  = (const float*)d_in[5];
  const float* ln_g  = (const float*)d_in[6];
  const float* ln_b  = (const float*)d_in[7];
  const float* W_fc1 = (const float*)d_in[8];
  const float* b_fc1 = (const float*)d_in[9];
  const float* W_fc2 = (const float*)d_in[10];
  const float* b_fc2 = (const float*)d_in[11];
  const float* W_out = (const float*)d_in[12];
  const float* b_out = (const float*)d_in[13];
  float* outp = (float*)d_out;

  float* base = nullptr;
  cudaGetSymbolAddress((void**)&base, g_scratch);
  float* gq    = base;
  float* gk    = base + SZ_;
  float* gv    = base + 2 * SZ_;
  float* go    = base + 3 * SZ_;
  float* gp    = base + 4 * SZ_;
  float* gh    = base + 5 * SZ_;
  float* gh2   = base + 6 * SZ_;
  float* gpool = base + 7 * SZ_;
  float* gfc1  = gpool + B_ * D_;
  float* gfc2  = gfc1 + B_ * F_;

  const int smem_attn = 2 * 32 * KT_STRIDE * (int)sizeof(float);  // 131328 B
  cudaFuncSetAttribute((const void*)attn_kernel,
                       cudaFuncAttributeMaxDynamicSharedMemorySize, smem_attn);

  dim3 gP(D_ / 128, ROWS_ / 128);  // projections: [32768,256]

  // ---- self-attention block ----
  sgemm_bias_kernel<<<gP, 256>>>(trg, W_sa,           b_sa,        gq, ROWS_, D_, D_, 0);
  sgemm_bias_kernel<<<gP, 256>>>(trg, W_sa + 65536,   b_sa + 256,  gk, ROWS_, D_, D_, 0);
  sgemm_bias_kernel<<<gP, 256>>>(trg, W_sa + 131072,  b_sa + 512,  gv, ROWS_, D_, D_, 0);
  attn_kernel<<<B_ * H_, 256, smem_attn>>>(gq, gk, gv, go);
  sgemm_bias_kernel<<<gP, 256>>>(go, W_sa + 196608,   b_sa + 768,  gp, ROWS_, D_, D_, 0);
  ln_residual_kernel<<<ROWS_ / 8, 256>>>(trg, gp, ln_g, ln_b, gh);

  // ---- cross-attention block ----
  sgemm_bias_kernel<<<gP, 256>>>(gh,  W_ea,           b_ea,        gq, ROWS_, D_, D_, 0);
  sgemm_bias_kernel<<<gP, 256>>>(src, W_ea + 65536,   b_ea + 256,  gk, ROWS_, D_, D_, 0);
  sgemm_bias_kernel<<<gP, 256>>>(src, W_ea + 131072,  b_ea + 512,  gv, ROWS_, D_, D_, 0);
  attn_kernel<<<B_ * H_, 256, smem_attn>>>(gq, gk, gv, go);
  sgemm_bias_kernel<<<gP, 256>>>(go, W_ea + 196608,   b_ea + 768,  gp, ROWS_, D_, D_, 0);
  ln_residual_kernel<<<ROWS_ / 8, 256>>>(gh, gp, ln_g, ln_b, gh2);

  // ---- pooling + head ----
  pool_kernel<<<B_, 256>>>(gh2, gpool);
  dim3 gF(F_ / 128, 1);  // M=64 -> 1 row-tile with guards
  sgemm_bias_kernel<<<gF, 256>>>(gpool, W_fc1, b_fc1, gfc1, B_, F_, D_, 1);
  sgemm_bias_kernel<<<gF, 256>>>(gfc1,  W_fc2, b_fc2, gfc2, B_, F_, F_, 1);
  fcout_kernel<<<1, 128>>>(gfc2, W_out, b_out, outp);
}